// round 16
// baseline (speedup 1.0000x reference)
#include <cuda_runtime.h>
#include <cuda_fp16.h>
#include <math.h>

#define NB 8
#define NTOK 4096
#define NC 256
#define NH 8
#define CHD 32
#define IMG 64
#define QLD 768   // qkv row stride (3*C), in elements
#define KVCH 16   // kv token chunks (256 tokens each)

// ---------------- scratch (device globals; no allocation allowed) -------------
__device__ __half g_xgh[NB * NTOK * NC];         // fp16 BN+hardswish
__device__ __half g_qkvh[NB * NTOK * 3 * NC];    // fp16 qkv
__device__ float g_csump[KVCH * NB * NH * CHD];  // per-chunk sum(exp(k))
__device__ float g_kvp[KVCH * NB * NH * CHD * CHD];
__device__ __half g_kvh[NB * NH * CHD * CHD];    // normalized+scaled kv^T fp16
__device__ __half g_preh[NB * NTOK * NC];        // fp16 pre-proj
__device__ __half g_wqh[QLD * NC];               // fp16 qkv_w
__device__ __half g_wph[NC * NC];                // fp16 proj_w
__device__ unsigned g_cnt[NB * NH];              // last-block counters (self-reset)

// ---------------- K0: BN+hardswish -> fp16  AND  weights -> fp16 (one launch) ---
#define PREP_BN_BLOCKS 8192   // NB*NTOK*NC/4/256
__global__ __launch_bounds__(256) void k_prep(const float* __restrict__ x,
                                              const float* __restrict__ gamma,
                                              const float* __restrict__ beta,
                                              const float* __restrict__ wq,
                                              const float* __restrict__ wp) {
    if (blockIdx.x < PREP_BN_BLOCKS) {
        int i = blockIdx.x * 256 + threadIdx.x;    // float4 index
        float4 v = ((const float4*)x)[i];
        int c0 = (i & 63) * 4;
        const float inv = rsqrtf(1.0f + 1e-5f);
        float* f = (float*)&v;
        __half o[4];
#pragma unroll
        for (int j = 0; j < 4; j++) {
            float xb = f[j] * (gamma[c0 + j] * inv) + beta[c0 + j];
            o[j] = __float2half_rn(xb * fminf(fmaxf(xb + 3.0f, 0.0f), 6.0f) * (1.0f / 6.0f));
        }
        *(uint2*)&g_xgh[(size_t)i * 4] = *(uint2*)o;
    } else {
        int i = (blockIdx.x - PREP_BN_BLOCKS) * 256 + threadIdx.x;
        if (i < QLD * NC) g_wqh[i] = __float2half_rn(wq[i]);
        if (i < NC * NC)  g_wph[i] = __float2half_rn(wp[i]);
    }
}

// ---------------- shared MMA helpers --------------------------------------------
__device__ __forceinline__ void cpa16(void* dst, const void* src) {
    unsigned d = (unsigned)__cvta_generic_to_shared(dst);
    asm volatile("cp.async.cg.shared.global [%0], [%1], 16;\n" :: "r"(d), "l"(src));
}
__device__ __forceinline__ void cp_commit() { asm volatile("cp.async.commit_group;\n"); }

__device__ __forceinline__ void ldsm4(unsigned* r, const __half* p) {
    unsigned a = (unsigned)__cvta_generic_to_shared(p);
    asm volatile("ldmatrix.sync.aligned.m8n8.x4.shared.b16 {%0,%1,%2,%3}, [%4];"
                 : "=r"(r[0]), "=r"(r[1]), "=r"(r[2]), "=r"(r[3]) : "r"(a));
}
__device__ __forceinline__ void ldsm4t(unsigned* r, const __half* p) {
    unsigned a = (unsigned)__cvta_generic_to_shared(p);
    asm volatile("ldmatrix.sync.aligned.m8n8.x4.trans.shared.b16 {%0,%1,%2,%3}, [%4];"
                 : "=r"(r[0]), "=r"(r[1]), "=r"(r[2]), "=r"(r[3]) : "r"(a));
}

__device__ __forceinline__ void mma16(float* c, const unsigned* a, const unsigned* b) {
    asm volatile(
        "mma.sync.aligned.m16n8k16.row.col.f32.f16.f16.f32 "
        "{%0,%1,%2,%3}, {%4,%5,%6,%7}, {%8,%9}, {%0,%1,%2,%3};"
        : "+f"(c[0]), "+f"(c[1]), "+f"(c[2]), "+f"(c[3])
        : "r"(a[0]), "r"(a[1]), "r"(a[2]), "r"(a[3]), "r"(b[0]), "r"(b[1]));
}

// ---------------- fp16 tensor-core GEMM, 3-stage pipeline ----------------------
#define BM 128
#define BN 128
#define BK 64     // halves per chunk (128 bytes per row)
#define SSTH 72   // smem row stride (halves): 144B -> 16B-aligned, LDSM conflict-free
#define NSTG 3
#define OST 136   // epilogue smem tile row stride (halves): conflict-free STS

extern __shared__ __align__(16) __half smem_h[];

// HOUT=true: fp16 output via smem-staged coalesced stores (bias must be null).
// HOUT=false: fp32 output direct (+bias).
template <bool HOUT>
__global__ __launch_bounds__(256, 2) void k_gemm_fp16(const __half* __restrict__ A,
                                                      const __half* __restrict__ W,
                                                      void* __restrict__ Cv,
                                                      int M, int Nd, int K,
                                                      const float* __restrict__ bias) {
    int tid = threadIdx.x;
    int m0 = blockIdx.y * BM, n0 = blockIdx.x * BN;
    int warp = tid >> 5, lane = tid & 31;
    int g = lane >> 2, t = lane & 3;
    int wm = (warp >> 2) * 64;
    int wn = (warp & 3) * 32;

    int al_row = lane & 15;
    int al_col = (lane >> 4) << 3;
    int bl_row = (lane & 7) + ((lane >> 4) << 3);
    int bl_col = ((lane >> 3) & 1) << 3;

    float acc[4][4][4];
#pragma unroll
    for (int mt = 0; mt < 4; mt++)
#pragma unroll
        for (int nt = 0; nt < 4; nt++)
#pragma unroll
            for (int r = 0; r < 4; r++) acc[mt][nt][r] = 0.0f;

    const int nch = K >> 6;

    auto issue = [&](int c, int stage) {
        if (c < nch) {
            __half* as = smem_h + stage * (2 * BM * SSTH);
            __half* bs = as + BM * SSTH;
            int k0 = c * BK;
#pragma unroll
            for (int j = 0; j < 4; j++) {
                int ci = tid + 256 * j;
                int row = ci >> 3;
                int kc = (ci & 7) << 3;
                cpa16(as + row * SSTH + kc, A + (size_t)(m0 + row) * K + k0 + kc);
                cpa16(bs + row * SSTH + kc, W + (size_t)(n0 + row) * K + k0 + kc);
            }
        }
        cp_commit();
    };

    issue(0, 0);
    issue(1, 1);

    for (int c = 0; c < nch; c++) {
        asm volatile("cp.async.wait_group 1;\n");
        __syncthreads();
        issue(c + 2, (c + 2) % NSTG);

        const __half* as = smem_h + (c % NSTG) * (2 * BM * SSTH);
        const __half* bs = as + BM * SSTH;
#pragma unroll
        for (int ks = 0; ks < 4; ks++) {
            int kb = ks * 16;
            unsigned af[4][4], bfr[2][4];
#pragma unroll
            for (int mt = 0; mt < 4; mt++)
                ldsm4(af[mt], as + (wm + mt * 16 + al_row) * SSTH + kb + al_col);
#pragma unroll
            for (int p = 0; p < 2; p++)
                ldsm4(bfr[p], bs + (wn + p * 16 + bl_row) * SSTH + kb + bl_col);
#pragma unroll
            for (int mt = 0; mt < 4; mt++)
#pragma unroll
                for (int nt = 0; nt < 4; nt++)
                    mma16(acc[mt][nt], af[mt], bfr[nt >> 1] + (nt & 1) * 2);
        }
    }

    if (HOUT) {
        __syncthreads();
        __half* os = smem_h;
#pragma unroll
        for (int mt = 0; mt < 4; mt++)
#pragma unroll
            for (int nt = 0; nt < 4; nt++) {
                int col = wn + nt * 8 + 2 * t;
                int row = wm + mt * 16 + g;
                *(__half2*)&os[row * OST + col] =
                    __floats2half2_rn(acc[mt][nt][0], acc[mt][nt][1]);
                *(__half2*)&os[(row + 8) * OST + col] =
                    __floats2half2_rn(acc[mt][nt][2], acc[mt][nt][3]);
            }
        __syncthreads();
        __half* Ch = (__half*)Cv;
#pragma unroll
        for (int j = 0; j < 8; j++) {
            int ci = tid + 256 * j;
            int row = ci >> 4;
            int hc = (ci & 15) << 3;
            *(uint4*)&Ch[(size_t)(m0 + row) * Nd + n0 + hc] =
                *(uint4*)&os[row * OST + hc];
        }
    } else {
#pragma unroll
        for (int mt = 0; mt < 4; mt++)
#pragma unroll
            for (int nt = 0; nt < 4; nt++) {
                int col = n0 + wn + nt * 8 + 2 * t;
                float b0 = bias ? bias[col] : 0.0f;
                float b1 = bias ? bias[col + 1] : 0.0f;
                int row0 = m0 + wm + mt * 16 + g;
                float* Cf = (float*)Cv;
                float2 o0 = make_float2(acc[mt][nt][0] + b0, acc[mt][nt][1] + b1);
                float2 o1 = make_float2(acc[mt][nt][2] + b0, acc[mt][nt][3] + b1);
                *(float2*)&Cf[(size_t)row0 * Nd + col] = o0;
                *(float2*)&Cf[(size_t)(row0 + 8) * Nd + col] = o1;
            }
    }
}

// ---------------- K3: kv = exp(k)^T v via tensor cores + fused final reduce ----
// Both operands token-major -> ldmatrix.x4.trans. M=k-chan 32, N=v-chan 32, K=tokens.
// The LAST block per bh (threadfence+atomic count) reduces all partials into g_kvh.
#define EKS 40    // smem row stride (halves): 80B -> all 8 rows in distinct 16B groups
__global__ __launch_bounds__(256) void k_kv() {
    int chunk = blockIdx.x;            // 0..KVCH-1 (256 tokens each)
    int bh = blockIdx.y;
    int b = bh >> 3, head = bh & 7;

    __shared__ __align__(16) float red[8192];     // 32 KB; fp16 tiles aliased inside
    __shared__ float sred[32 * 17];
    __shared__ int is_last;
    __half* ek = (__half*)red;                    // [128][EKS]
    __half* vsm = ek + 128 * EKS;                 // [128][EKS]

    int tid = threadIdx.x;
    int warp = tid >> 5, lane = tid & 31;
    int g = lane >> 2, t = lane & 3;
    int c2 = (tid & 15) << 1;          // fill: channel pair
    int jj = tid >> 4;                 // fill: row group 0..15

    // trans-ldmatrix lane addressing
    int ta_row = (lane & 7) + ((lane >> 4) << 3);   // A(ek^T): token row
    int ta_col = ((lane >> 3) & 1) << 3;            // A: channel offset
    int tb_row = lane & 15;                         // B(v): token row
    int tb_col = (lane >> 4) << 3;                  // B: channel offset

    const __half* base = g_qkvh + (size_t)(b * NTOK + chunk * (NTOK / KVCH)) * QLD + head * 32;

    float acc[2][4][4];
#pragma unroll
    for (int mt = 0; mt < 2; mt++)
#pragma unroll
        for (int nt = 0; nt < 4; nt++)
#pragma unroll
            for (int r = 0; r < 4; r++) acc[mt][nt][r] = 0.0f;
    float sA = 0.0f, sB = 0.0f;

    for (int tch = 0; tch < (NTOK / KVCH) / 128; tch++) {
        const __half* tb = base + (size_t)tch * 128 * QLD;
#pragma unroll
        for (int it = 0; it < 8; it++) {
            int r = jj + it * 16;
            size_t off = (size_t)r * QLD + c2;
            float2 fk = __half22float2(*(const __half2*)&tb[off + 256]);
            float e0 = __expf(fk.x), e1 = __expf(fk.y);
            sA += e0; sB += e1;
            *(__half2*)&ek[r * EKS + c2] = __floats2half2_rn(e0, e1);
            *(__half2*)&vsm[r * EKS + c2] = *(const __half2*)&tb[off + 512];
        }
        __syncthreads();

        // warp w consumes tokens [w*16, w*16+16)
        int kr = warp * 16;
        unsigned af[2][4], bfr[2][4];
#pragma unroll
        for (int mt = 0; mt < 2; mt++)
            ldsm4t(af[mt], ek + (kr + ta_row) * EKS + mt * 16 + ta_col);
#pragma unroll
        for (int p = 0; p < 2; p++)
            ldsm4t(bfr[p], vsm + (kr + tb_row) * EKS + p * 16 + tb_col);
#pragma unroll
        for (int mt = 0; mt < 2; mt++)
#pragma unroll
            for (int nt = 0; nt < 4; nt++)
                mma16(acc[mt][nt], af[mt], bfr[nt >> 1] + (nt & 1) * 2);
        __syncthreads();                 // tiles free after this
    }

    sred[c2 * 17 + jj] = sA;
    sred[(c2 + 1) * 17 + jj] = sB;

    // per-warp 32x32 partials into red (aliases freed tiles)
#pragma unroll
    for (int mt = 0; mt < 2; mt++)
#pragma unroll
        for (int nt = 0; nt < 4; nt++)
#pragma unroll
            for (int r = 0; r < 4; r++) {
                int m = mt * 16 + g + ((r >> 1) << 3);   // k-channel
                int n = nt * 8 + 2 * t + (r & 1);        // v-channel
                red[warp * 1024 + m * 32 + n] = acc[mt][nt][r];
            }
    __syncthreads();

    for (int i = tid; i < 1024; i += 256) {
        float s = 0.0f;
#pragma unroll
        for (int gg = 0; gg < 8; gg++) s += red[gg * 1024 + i];
        g_kvp[((size_t)chunk * 64 + bh) * 1024 + i] = s;
    }
    if (tid < 32) {
        float ss = 0.0f;
#pragma unroll
        for (int j = 0; j < 16; j++) ss += sred[tid * 17 + j];
        g_csump[((size_t)chunk * 64 + bh) * 32 + tid] = ss;
    }

    // ---- last-block fused kvred (threadFenceReduction pattern) ----
    __threadfence();
    __syncthreads();
    if (tid == 0) {
        unsigned c = atomicAdd(&g_cnt[bh], 1u);
        is_last = (c == KVCH - 1);
    }
    __syncthreads();
    if (is_last) {
        const float scale = 0.1767766952966369f;   // 32^-0.5
        if (tid < 32) {
            float ss = 0.0f;
#pragma unroll
            for (int ch = 0; ch < KVCH; ch++)
                ss += g_csump[((size_t)ch * 64 + bh) * 32 + tid];
            sred[tid] = scale / ss;
        }
        __syncthreads();
#pragma unroll
        for (int j = 0; j < 4; j++) {
            int i = tid + 256 * j;             // 0..1023
            float s = 0.0f;
#pragma unroll
            for (int ch = 0; ch < KVCH; ch++)
                s += g_kvp[((size_t)ch * 64 + bh) * 1024 + i];
            int k = i >> 5, v = i & 31;
            g_kvh[bh * 1024 + v * 32 + k] = __float2half_rn(s * sred[k]);
        }
        if (tid == 0) g_cnt[bh] = 0;           // reset for next graph replay
    }
}

// ---------------- K3b: eff = q @ kvh^T via tensor cores -> g_preh --------------
#define EQS 40    // q smem row stride (halves)
#define EFFCH 16  // token chunks (256 tokens each)
__global__ __launch_bounds__(256) void k_eff() {
    int chunk = blockIdx.x;            // 0..EFFCH-1 (256 tokens each)
    int bh = blockIdx.y;
    int b = bh >> 3, head = bh & 7;

    __half* qs = smem_h;               // 256 x EQS
    __half* ks = smem_h + 256 * EQS;   // 32 x EQS (row=v, col=k)

    int tid = threadIdx.x;
    int warp = tid >> 5, lane = tid & 31;
    int g = lane >> 2, t = lane & 3;

    // stage q: 256 rows x 32 halves = 1024 16B chunks (4 per row)
    const __half* qg = g_qkvh + (size_t)(b * NTOK + chunk * 256) * QLD + head * 32;
#pragma unroll
    for (int j = 0; j < 4; j++) {
        int ci = tid + 256 * j;            // 0..1023
        int row = ci >> 2;                 // 0..255
        int hc = (ci & 3) << 3;
        cpa16(qs + row * EQS + hc, qg + (size_t)row * QLD + hc);
    }
    // stage kvh: 32 rows x 32 halves = 128 chunks (4 per row)
    if (tid < 128) {
        int row = tid >> 2;
        int hc = (tid & 3) << 3;
        cpa16(ks + row * EQS + hc, g_kvh + bh * 1024 + row * 32 + hc);
    }
    cp_commit();
    asm volatile("cp.async.wait_group 0;\n");
    __syncthreads();

    int al_row = lane & 15;
    int al_col = (lane >> 4) << 3;
    int bl_row = (lane & 7) + ((lane >> 4) << 3);
    int bl_col = ((lane >> 3) & 1) << 3;

    float acc[2][4][4];
#pragma unroll
    for (int mt = 0; mt < 2; mt++)
#pragma unroll
        for (int nt = 0; nt < 4; nt++)
#pragma unroll
            for (int r = 0; r < 4; r++) acc[mt][nt][r] = 0.0f;

#pragma unroll
    for (int kst = 0; kst < 2; kst++) {
        int kb = kst * 16;
        unsigned af[2][4], bfr[2][4];
#pragma unroll
        for (int mt = 0; mt < 2; mt++)
            ldsm4(af[mt], qs + (warp * 32 + mt * 16 + al_row) * EQS + kb + al_col);
#pragma unroll
        for (int p = 0; p < 2; p++)
            ldsm4(bfr[p], ks + (p * 16 + bl_row) * EQS + kb + bl_col);
#pragma unroll
        for (int mt = 0; mt < 2; mt++)
#pragma unroll
            for (int nt = 0; nt < 4; nt++)
                mma16(acc[mt][nt], af[mt], bfr[nt >> 1] + (nt & 1) * 2);
    }

    __syncthreads();
    __half* os = smem_h;               // 256 x 32 compact
#pragma unroll
    for (int mt = 0; mt < 2; mt++)
#pragma unroll
        for (int nt = 0; nt < 4; nt++) {
            int row = warp * 32 + mt * 16 + g;
            int col = nt * 8 + 2 * t;
            *(__half2*)&os[row * 32 + col] =
                __floats2half2_rn(acc[mt][nt][0], acc[mt][nt][1]);
            *(__half2*)&os[(row + 8) * 32 + col] =
                __floats2half2_rn(acc[mt][nt][2], acc[mt][nt][3]);
        }
    __syncthreads();

    __half* pg = g_preh + (size_t)(b * NTOK + chunk * 256) * NC + head * 32;
#pragma unroll
    for (int j = 0; j < 4; j++) {
        int ci = tid + 256 * j;            // 0..1023 chunks
        int row = ci >> 2;
        int hc = (ci & 3) << 3;
        *(uint4*)&pg[(size_t)row * NC + hc] = *(uint4*)&os[row * 32 + hc];
    }
}

// ---------------- K4: depthwise conv (smem v tile) + gating, adds to pre -------
extern __shared__ __align__(16) __half s_vt[];   // [nrows][64][32] halves (dynamic)

template <int KSZ>
__device__ __forceinline__ void conv_head(const __half* __restrict__ qg,   // stride QLD
                                          __half* __restrict__ pg,         // stride NC
                                          const __half* __restrict__ vt,
                                          const float* __restrict__ wsrc,
                                          float biasv) {
    const int P = KSZ / 2;

    float wreg[KSZ * KSZ];
#pragma unroll
    for (int i = 0; i < KSZ * KSZ; i++) wreg[i] = wsrc[i];

    float win[KSZ][KSZ];
#pragma unroll
    for (int dy = 0; dy < KSZ; dy++)
#pragma unroll
        for (int j = 0; j < KSZ; j++) win[dy][j] = 0.0f;

#pragma unroll
    for (int xx = 0; xx < P; xx++) {
#pragma unroll
        for (int dy = 0; dy < KSZ; dy++)
            win[dy][xx] = __half2float(vt[dy * 2048 + xx * 32]);
    }

    for (int xb = 0; xb < IMG; xb += KSZ) {
#pragma unroll
        for (int xi = 0; xi < KSZ; xi++) {
            int x = xb + xi;
            if (x < IMG) {                       // IMG % KSZ != 0: guard the tail
                const int slot_new = (xi + P) % KSZ;
                int xn = x + P;
                if (xn < IMG) {
#pragma unroll
                    for (int dy = 0; dy < KSZ; dy++)
                        win[dy][slot_new] = __half2float(vt[dy * 2048 + xn * 32]);
                } else {
#pragma unroll
                    for (int dy = 0; dy < KSZ; dy++) win[dy][slot_new] = 0.0f;
                }

                float q = __half2float(qg[(size_t)x * QLD]);
                float prev = __half2float(pg[(size_t)x * NC]);

                float acc = biasv;
#pragma unroll
                for (int dy = 0; dy < KSZ; dy++)
#pragma unroll
                    for (int dx = 0; dx < KSZ; dx++) {
                        const int slot = (xi + dx + 2 * KSZ - P) % KSZ;
                        acc += win[dy][slot] * wreg[dy * KSZ + dx];
                    }

                pg[(size_t)x * NC] = __float2half_rn(prev + q * acc);
            }
        }
    }
}

__global__ __launch_bounds__(256, 2) void k_conv_att(const float* __restrict__ w3,
                                                     const float* __restrict__ b3,
                                                     const float* __restrict__ w5,
                                                     const float* __restrict__ b5,
                                                     const float* __restrict__ w7,
                                                     const float* __restrict__ b7) {
    int yt = blockIdx.x;
    int head = blockIdx.y;
    int b = blockIdx.z;
    int lane = threadIdx.x & 31, w = threadIdx.x >> 5;
    int tid = threadIdx.x;

    __shared__ float bias_s[32];

    int P = (head < 2) ? 1 : (head < 5) ? 2 : 3;
    int nrows = 8 + 2 * P;
    int y0 = yt * 8;

    const __half* vglob = g_qkvh + (size_t)b * NTOK * QLD + 512 + head * 32;
    for (int idx = tid; idx < nrows * 64 * 16; idx += 256) {
        int rr = idx >> 10;
        int rem = idx & 1023;
        int xx = rem >> 4;
        int cc2 = (rem & 15) << 1;
        int yy = y0 - P + rr;
        __half2 val = __float2half2_rn(0.0f);
        if ((unsigned)yy < (unsigned)IMG)
            val = *(const __half2*)&vglob[(size_t)(yy * IMG + xx) * QLD + cc2];
        *(__half2*)&s_vt[(rr * 64 + xx) * 32 + cc2] = val;
    }

    int chb;
    const float* wp;
    const float* bp;
    if (head < 2)      { wp = w3; bp = b3; chb = head * 32; }
    else if (head < 5) { wp = w5; bp = b5; chb = head * 32 - 64; }
    else               { wp = w7; bp = b7; chb = head * 32 - 160; }
    int ntap = (head < 2) ? 9 : (head < 5) ? 25 : 49;
    if (tid < 32) bias_s[tid] = bp[chb + tid];
    __syncthreads();

    int y = y0 + w;
    const __half* qg = g_qkvh + (size_t)(b * NTOK + y * IMG) * QLD + head * 32 + lane;
    __half* pg = g_preh + (size_t)(b * NTOK + y * IMG) * NC + head * 32 + lane;
    const __half* vt = s_vt + (size_t)w * 2048 + lane;
    const float* wsrc = wp + (size_t)(chb + lane) * ntap;
    float biasv = bias_s[lane];

    if (head < 2)      conv_head<3>(qg, pg, vt, wsrc, biasv);
    else if (head < 5) conv_head<5>(qg, pg, vt, wsrc, biasv);
    else               conv_head<7>(qg, pg, vt, wsrc, biasv);
}

// ---------------- launch -------------------------------------------------------
extern "C" void kernel_launch(void* const* d_in, const int* in_sizes, int n_in,
                              void* d_out, int out_size) {
    const float* x      = (const float*)d_in[0];
    const float* qkv_w  = (const float*)d_in[1];
    const float* proj_w = (const float*)d_in[2];
    const float* proj_b = (const float*)d_in[3];
    const float* gamma  = (const float*)d_in[4];
    const float* beta   = (const float*)d_in[5];
    const float* w3     = (const float*)d_in[6];
    const float* b3     = (const float*)d_in[7];
    const float* w5     = (const float*)d_in[8];
    const float* b5     = (const float*)d_in[9];
    const float* w7     = (const float*)d_in[10];
    const float* b7     = (const float*)d_in[11];
    float* out = (float*)d_out;

    void *p_xg, *p_qkv, *p_pre, *p_wq, *p_wp;
    cudaGetSymbolAddress(&p_xg, g_xgh);
    cudaGetSymbolAddress(&p_qkv, g_qkvh);
    cudaGetSymbolAddress(&p_pre, g_preh);
    cudaGetSymbolAddress(&p_wq, g_wqh);
    cudaGetSymbolAddress(&p_wp, g_wph);

    static int smem_set = 0;
    const int SMEM_BYTES = NSTG * 2 * BM * SSTH * 2;   // 110592
    const int SMEM_CONV = 14 * 64 * 32 * 2;            // 57344 (dynamic v tile)
    const int SMEM_EFF = (256 * EQS + 32 * EQS) * 2;   // 23040
    if (!smem_set) {
        cudaFuncSetAttribute(k_gemm_fp16<true>,
                             cudaFuncAttributeMaxDynamicSharedMemorySize, SMEM_BYTES);
        cudaFuncSetAttribute(k_gemm_fp16<false>,
                             cudaFuncAttributeMaxDynamicSharedMemorySize, SMEM_BYTES);
        cudaFuncSetAttribute(k_conv_att,
                             cudaFuncAttributeMaxDynamicSharedMemorySize, SMEM_CONV);
        cudaFuncSetAttribute(k_eff,
                             cudaFuncAttributeMaxDynamicSharedMemorySize, SMEM_EFF);
        smem_set = 1;
    }

    // 0. BN+hardswish -> fp16 AND weights -> fp16
    k_prep<<<PREP_BN_BLOCKS + (QLD * NC + 255) / 256, 256>>>(x, gamma, beta,
                                                             qkv_w, proj_w);

    // 1. qkv = xg @ qkv_w^T   [32768 x 768], K=256
    k_gemm_fp16<true><<<dim3(QLD / BN, NB * NTOK / BM), 256, SMEM_BYTES>>>(
        (const __half*)p_xg, (const __half*)p_wq, p_qkv,
        NB * NTOK, QLD, NC, nullptr);

    // 2. kv via tensor cores + sum(exp(k)) + fused last-block reduce -> g_kvh
    k_kv<<<dim3(KVCH, 64), 256>>>();

    // 3. eff = q @ kvh^T (tensor cores) -> g_preh
    k_eff<<<dim3(EFFCH, 64), 256, SMEM_EFF>>>();

    // 4. conv + gating, accumulate into g_preh
    k_conv_att<<<dim3(8, 8, 8), 256, SMEM_CONV>>>(w3, b3, w5, b5, w7, b7);

    // 5. out = pre @ proj_w^T + proj_b   [32768 x 256]
    k_gemm_fp16<false><<<dim3(NC / BN, NB * NTOK / BM), 256, SMEM_BYTES>>>(
        (const __half*)p_pre, (const __half*)p_wp, out,
        NB * NTOK, NC, NC, proj_b);
}